// round 6
// baseline (speedup 1.0000x reference)
#include <cuda_runtime.h>
#include <cstdint>

#define BB   8
#define LL   4096
#define KNN  16
#define DD   128

// scratch for neighbor indices (no cudaMalloc allowed)
__device__ int g_nbr[BB * LL * KNN];

// ---------------------------------------------------------------------------
// Kernel 1: warp-cooperative exact top-16 KNN + euclidian output.
// One WARP per query; sorted top-16 distributed across lanes 0..15.
// Block = 512 threads (16 queries) with 48KB smem -> 2048 threads/SM resident.
// ---------------------------------------------------------------------------
__global__ __launch_bounds__(512)
void knn_kernel(const float* __restrict__ frame, float* __restrict__ out_euclid)
{
    __shared__ float sx[LL];
    __shared__ float sy[LL];
    __shared__ float sz[LL];

    const int b     = blockIdx.y;
    const int lane  = threadIdx.x & 31;
    const int wib   = threadIdx.x >> 5;            // warp in block: 0..15
    const int q     = blockIdx.x * 16 + wib;       // gridDim.x = 256
    const float* fb = frame + (size_t)b * LL * 12;

    // stage centers: frame[b, j, 0, 0..2] (float4 load, drop .w)
    for (int j = threadIdx.x; j < LL; j += 512) {
        const float4 v = *reinterpret_cast<const float4*>(fb + j * 12);
        sx[j] = v.x;
        sy[j] = v.y;
        sz[j] = v.z;
    }
    __syncthreads();

    const float qx = sx[q], qy = sy[q], qz = sz[q];

    const unsigned FULL = 0xffffffffu;
    const float INF = __int_as_float(0x7f800000);

    // distributed top-16: lanes 0..15 hold the sorted list; lanes 16..31
    // permanently hold +inf so insertion-position ballots are well-formed.
    float lk  = INF;   // key (distance)
    int   li  = -1;    // neighbor index
    float thr = INF;   // current 16th-best distance (lane 15's key)

    // insert all candidates flagged in `mask` (lane s holds distance `dist`,
    // global index jbase+s), ascending lane order == ascending j order.
    // strict '<' everywhere => jax.lax.top_k stable tie semantics.
    auto insert_all = [&](unsigned mask, float dist, int jbase) {
        while (mask) {
            const int   s  = __ffs(mask) - 1;
            const float cd = __shfl_sync(FULL, dist, s);
            const int   ci = jbase + s;

            const float up_d = __shfl_up_sync(FULL, lk, 1);
            const int   up_i = __shfl_up_sync(FULL, li, 1);
            const unsigned posb = __ballot_sync(FULL, cd < lk);
            const int p = __ffs(posb) - 1;      // insertion position (<=15)

            if (lane < 16) {
                if (lane == p)      { lk = cd;   li = ci;   }
                else if (lane > p)  { lk = up_d; li = up_i; }
            }
            thr = __shfl_sync(FULL, lk, 15);

            mask &= ~(1u << s);
            mask &= __ballot_sync(FULL, dist < thr);
        }
    };

    for (int j0 = 0; j0 < LL; j0 += 64) {
        const int jA = j0 + lane;
        const int jB = j0 + 32 + lane;

        const float axd = qx - sx[jA];
        const float ayd = qy - sy[jA];
        const float azd = qz - sz[jA];
        const float bxd = qx - sx[jB];
        const float byd = qy - sy[jB];
        const float bzd = qz - sz[jB];
        const float dA = fmaf(azd, azd, fmaf(ayd, ayd, axd * axd));
        const float dB = fmaf(bzd, bzd, fmaf(byd, byd, bxd * bxd));

        const unsigned mA = __ballot_sync(FULL, dA < thr);
        if (mA) insert_all(mA, dA, j0);
        const unsigned mB = __ballot_sync(FULL, dB < thr);
        if (mB) insert_all(mB, dB, j0 + 32);
    }

    // epilogue: lanes 0..15 each own one neighbor
    if (lane < KNN) {
        const int nb = li;
        const size_t base = ((size_t)b * LL + q) * KNN;
        g_nbr[base + lane] = nb;

        const float dx = sx[nb] - qx;
        const float dy = sy[nb] - qy;
        const float dz = sz[nb] - qz;

        const float* fq = fb + q * 12;   // rotation rows, broadcast across lanes
        const float e0 = fmaf(dz, fq[9],  fmaf(dy, fq[6], dx * fq[3]));
        const float e1 = fmaf(dz, fq[10], fmaf(dy, fq[7], dx * fq[4]));
        const float e2 = fmaf(dz, fq[11], fmaf(dy, fq[8], dx * fq[5]));

        float* o = out_euclid + (base + lane) * 3;
        o[0] = e0; o[1] = e1; o[2] = e2;
    }
}

// ---------------------------------------------------------------------------
// Kernel 2: gather attr rows. One warp per TWO (b,l,k) rows; lane i copies
// float4 i of each row (2 independent LDG.128/STG.128 per lane for MLP).
// ---------------------------------------------------------------------------
__global__ __launch_bounds__(256)
void gather_kernel(const float* __restrict__ attr, float* __restrict__ out_attr)
{
    const int warp = (blockIdx.x * blockDim.x + threadIdx.x) >> 5;
    const int lane = threadIdx.x & 31;
    const int row0 = warp * 2;
    if (row0 >= BB * LL * KNN) return;

    const int b = row0 / (LL * KNN);           // rows row0, row0+1 share b
    const int2 jj = *reinterpret_cast<const int2*>(g_nbr + row0);

    const float4* s0 = reinterpret_cast<const float4*>(attr + ((size_t)b * LL + jj.x) * DD);
    const float4* s1 = reinterpret_cast<const float4*>(attr + ((size_t)b * LL + jj.y) * DD);
    float4* d0 = reinterpret_cast<float4*>(out_attr + (size_t)row0 * DD);
    float4* d1 = d0 + DD / 4;

    const float4 v0 = s0[lane];
    const float4 v1 = s1[lane];
    d0[lane] = v0;
    d1[lane] = v1;
}

extern "C" void kernel_launch(void* const* d_in, const int* in_sizes, int n_in,
                              void* d_out, int out_size)
{
    const float* frame = (const float*)d_in[0];
    const float* attr  = (const float*)d_in[1];
    if (n_in >= 2 && in_sizes[0] == BB * LL * DD) {   // defensive order check
        attr  = (const float*)d_in[0];
        frame = (const float*)d_in[1];
    }

    float* out        = (float*)d_out;
    float* out_euclid = out;                               // B*L*K*3
    float* out_attr   = out + (size_t)BB * LL * KNN * 3;   // B*L*K*D

    knn_kernel<<<dim3(LL / 16, BB), 512>>>(frame, out_euclid);

    const int rows = BB * LL * KNN;                        // 524288 rows
    gather_kernel<<<rows / 16, 256>>>(attr, out_attr);     // 2 rows per warp
}

// round 9
// speedup vs baseline: 1.0031x; 1.0031x over previous
#include <cuda_runtime.h>
#include <cstdint>

#define BB   8
#define LL   4096
#define KNN  16
#define DD   128

// scratch for neighbor indices (no cudaMalloc allowed)
__device__ int g_nbr[BB * LL * KNN];

// ---------------------------------------------------------------------------
// Kernel 1: warp-cooperative exact top-16 KNN + euclidian output.
// One WARP per query; sorted top-16 distributed across lanes 0..15.
// Block = 512 threads (16 queries) with 48KB smem -> 2048 threads/SM resident.
// ---------------------------------------------------------------------------
__global__ __launch_bounds__(512)
void knn_kernel(const float* __restrict__ frame, float* __restrict__ out_euclid)
{
    __shared__ float sx[LL];
    __shared__ float sy[LL];
    __shared__ float sz[LL];

    const int b     = blockIdx.y;
    const int lane  = threadIdx.x & 31;
    const int wib   = threadIdx.x >> 5;            // warp in block: 0..15
    const int q     = blockIdx.x * 16 + wib;       // gridDim.x = 256
    const float* fb = frame + (size_t)b * LL * 12;

    // stage centers: frame[b, j, 0, 0..2] (float4 load, drop .w)
    for (int j = threadIdx.x; j < LL; j += 512) {
        const float4 v = *reinterpret_cast<const float4*>(fb + j * 12);
        sx[j] = v.x;
        sy[j] = v.y;
        sz[j] = v.z;
    }
    __syncthreads();

    const float qx = sx[q], qy = sy[q], qz = sz[q];

    const unsigned FULL = 0xffffffffu;
    const float INF = __int_as_float(0x7f800000);

    // distributed top-16: lanes 0..15 hold the sorted list; lanes 16..31
    // permanently hold +inf so insertion-position ballots are well-formed.
    float lk  = INF;   // key (distance)
    int   li  = -1;    // neighbor index
    float thr = INF;   // current 16th-best distance (lane 15's key)

    // insert all candidates flagged in `mask` (lane s holds distance `dist`,
    // global index jbase+s), ascending lane order == ascending j order.
    // strict '<' everywhere => jax.lax.top_k stable tie semantics.
    auto insert_all = [&](unsigned mask, float dist, int jbase) {
        while (mask) {
            const int   s  = __ffs(mask) - 1;
            const float cd = __shfl_sync(FULL, dist, s);
            const int   ci = jbase + s;

            const float up_d = __shfl_up_sync(FULL, lk, 1);
            const int   up_i = __shfl_up_sync(FULL, li, 1);
            const unsigned posb = __ballot_sync(FULL, cd < lk);
            const int p = __ffs(posb) - 1;      // insertion position (<=15)

            if (lane < 16) {
                if (lane == p)      { lk = cd;   li = ci;   }
                else if (lane > p)  { lk = up_d; li = up_i; }
            }
            thr = __shfl_sync(FULL, lk, 15);

            mask &= ~(1u << s);
            mask &= __ballot_sync(FULL, dist < thr);
        }
    };

    for (int j0 = 0; j0 < LL; j0 += 64) {
        const int jA = j0 + lane;
        const int jB = j0 + 32 + lane;

        const float axd = qx - sx[jA];
        const float ayd = qy - sy[jA];
        const float azd = qz - sz[jA];
        const float bxd = qx - sx[jB];
        const float byd = qy - sy[jB];
        const float bzd = qz - sz[jB];
        const float dA = fmaf(azd, azd, fmaf(ayd, ayd, axd * axd));
        const float dB = fmaf(bzd, bzd, fmaf(byd, byd, bxd * bxd));

        const unsigned mA = __ballot_sync(FULL, dA < thr);
        if (mA) insert_all(mA, dA, j0);
        const unsigned mB = __ballot_sync(FULL, dB < thr);
        if (mB) insert_all(mB, dB, j0 + 32);
    }

    // epilogue: lanes 0..15 each own one neighbor
    if (lane < KNN) {
        const int nb = li;
        const size_t base = ((size_t)b * LL + q) * KNN;
        g_nbr[base + lane] = nb;

        const float dx = sx[nb] - qx;
        const float dy = sy[nb] - qy;
        const float dz = sz[nb] - qz;

        const float* fq = fb + q * 12;   // rotation rows, broadcast across lanes
        const float e0 = fmaf(dz, fq[9],  fmaf(dy, fq[6], dx * fq[3]));
        const float e1 = fmaf(dz, fq[10], fmaf(dy, fq[7], dx * fq[4]));
        const float e2 = fmaf(dz, fq[11], fmaf(dy, fq[8], dx * fq[5]));

        float* o = out_euclid + (base + lane) * 3;
        o[0] = e0; o[1] = e1; o[2] = e2;
    }
}

// ---------------------------------------------------------------------------
// Kernel 2: gather attr rows. One warp per TWO (b,l,k) rows; lane i copies
// float4 i of each row (2 independent LDG.128/STG.128 per lane for MLP).
// ---------------------------------------------------------------------------
__global__ __launch_bounds__(256)
void gather_kernel(const float* __restrict__ attr, float* __restrict__ out_attr)
{
    const int warp = (blockIdx.x * blockDim.x + threadIdx.x) >> 5;
    const int lane = threadIdx.x & 31;
    const int row0 = warp * 2;
    if (row0 >= BB * LL * KNN) return;

    const int b = row0 / (LL * KNN);           // rows row0, row0+1 share b
    const int2 jj = *reinterpret_cast<const int2*>(g_nbr + row0);

    const float4* s0 = reinterpret_cast<const float4*>(attr + ((size_t)b * LL + jj.x) * DD);
    const float4* s1 = reinterpret_cast<const float4*>(attr + ((size_t)b * LL + jj.y) * DD);
    float4* d0 = reinterpret_cast<float4*>(out_attr + (size_t)row0 * DD);
    float4* d1 = d0 + DD / 4;

    const float4 v0 = s0[lane];
    const float4 v1 = s1[lane];
    d0[lane] = v0;
    d1[lane] = v1;
}

extern "C" void kernel_launch(void* const* d_in, const int* in_sizes, int n_in,
                              void* d_out, int out_size)
{
    const float* frame = (const float*)d_in[0];
    const float* attr  = (const float*)d_in[1];
    if (n_in >= 2 && in_sizes[0] == BB * LL * DD) {   // defensive order check
        attr  = (const float*)d_in[0];
        frame = (const float*)d_in[1];
    }

    float* out        = (float*)d_out;
    float* out_euclid = out;                               // B*L*K*3
    float* out_attr   = out + (size_t)BB * LL * KNN * 3;   // B*L*K*D

    knn_kernel<<<dim3(LL / 16, BB), 512>>>(frame, out_euclid);

    const int rows = BB * LL * KNN;                        // 524288 rows
    gather_kernel<<<rows / 16, 256>>>(attr, out_attr);     // 2 rows per warp
}

// round 11
// speedup vs baseline: 1.0035x; 1.0004x over previous
#include <cuda_runtime.h>
#include <cstdint>

#define BB   8
#define LL   4096
#define KNN  16
#define DD   128

// scratch for neighbor indices (no cudaMalloc allowed)
__device__ int g_nbr[BB * LL * KNN];

// ---------------------------------------------------------------------------
// Kernel 1: warp-cooperative exact top-16 KNN + euclidian output.
// One WARP per query; sorted top-16 distributed across lanes 0..15.
// Block = 512 threads (16 queries) with 48KB smem -> 2048 threads/SM resident.
// ---------------------------------------------------------------------------
__global__ __launch_bounds__(512)
void knn_kernel(const float* __restrict__ frame, float* __restrict__ out_euclid)
{
    __shared__ float sx[LL];
    __shared__ float sy[LL];
    __shared__ float sz[LL];

    const int b     = blockIdx.y;
    const int lane  = threadIdx.x & 31;
    const int wib   = threadIdx.x >> 5;            // warp in block: 0..15
    const int q     = blockIdx.x * 16 + wib;       // gridDim.x = 256
    const float* fb = frame + (size_t)b * LL * 12;

    // stage centers: frame[b, j, 0, 0..2] (float4 load, drop .w)
    for (int j = threadIdx.x; j < LL; j += 512) {
        const float4 v = *reinterpret_cast<const float4*>(fb + j * 12);
        sx[j] = v.x;
        sy[j] = v.y;
        sz[j] = v.z;
    }
    __syncthreads();

    const float qx = sx[q], qy = sy[q], qz = sz[q];

    const unsigned FULL = 0xffffffffu;
    const float INF = __int_as_float(0x7f800000);

    // distributed top-16: lanes 0..15 hold the sorted list; lanes 16..31
    // permanently hold +inf so insertion-position ballots are well-formed.
    float lk  = INF;   // key (distance)
    int   li  = -1;    // neighbor index
    float thr = INF;   // current 16th-best distance (lane 15's key)

    // insert all candidates flagged in `mask` (lane s holds distance `dist`,
    // global index jbase+s), ascending lane order == ascending j order.
    // strict '<' everywhere => jax.lax.top_k stable tie semantics.
    auto insert_all = [&](unsigned mask, float dist, int jbase) {
        while (mask) {
            const int   s  = __ffs(mask) - 1;
            const float cd = __shfl_sync(FULL, dist, s);
            const int   ci = jbase + s;

            const float up_d = __shfl_up_sync(FULL, lk, 1);
            const int   up_i = __shfl_up_sync(FULL, li, 1);
            const unsigned posb = __ballot_sync(FULL, cd < lk);
            const int p = __ffs(posb) - 1;      // insertion position (<=15)

            if (lane < 16) {
                if (lane == p)      { lk = cd;   li = ci;   }
                else if (lane > p)  { lk = up_d; li = up_i; }
            }
            thr = __shfl_sync(FULL, lk, 15);

            mask &= ~(1u << s);
            mask &= __ballot_sync(FULL, dist < thr);
        }
    };

    for (int j0 = 0; j0 < LL; j0 += 64) {
        const int jA = j0 + lane;
        const int jB = j0 + 32 + lane;

        const float axd = qx - sx[jA];
        const float ayd = qy - sy[jA];
        const float azd = qz - sz[jA];
        const float bxd = qx - sx[jB];
        const float byd = qy - sy[jB];
        const float bzd = qz - sz[jB];
        const float dA = fmaf(azd, azd, fmaf(ayd, ayd, axd * axd));
        const float dB = fmaf(bzd, bzd, fmaf(byd, byd, bxd * bxd));

        const unsigned mA = __ballot_sync(FULL, dA < thr);
        if (mA) insert_all(mA, dA, j0);
        const unsigned mB = __ballot_sync(FULL, dB < thr);
        if (mB) insert_all(mB, dB, j0 + 32);
    }

    // epilogue: lanes 0..15 each own one neighbor
    if (lane < KNN) {
        const int nb = li;
        const size_t base = ((size_t)b * LL + q) * KNN;
        g_nbr[base + lane] = nb;

        const float dx = sx[nb] - qx;
        const float dy = sy[nb] - qy;
        const float dz = sz[nb] - qz;

        const float* fq = fb + q * 12;   // rotation rows, broadcast across lanes
        const float e0 = fmaf(dz, fq[9],  fmaf(dy, fq[6], dx * fq[3]));
        const float e1 = fmaf(dz, fq[10], fmaf(dy, fq[7], dx * fq[4]));
        const float e2 = fmaf(dz, fq[11], fmaf(dy, fq[8], dx * fq[5]));

        float* o = out_euclid + (base + lane) * 3;
        o[0] = e0; o[1] = e1; o[2] = e2;
    }
}

// ---------------------------------------------------------------------------
// Kernel 2: gather attr rows. One warp per TWO (b,l,k) rows; lane i copies
// float4 i of each row (2 independent LDG.128/STG.128 per lane for MLP).
// ---------------------------------------------------------------------------
__global__ __launch_bounds__(256)
void gather_kernel(const float* __restrict__ attr, float* __restrict__ out_attr)
{
    const int warp = (blockIdx.x * blockDim.x + threadIdx.x) >> 5;
    const int lane = threadIdx.x & 31;
    const int row0 = warp * 2;
    if (row0 >= BB * LL * KNN) return;

    const int b = row0 / (LL * KNN);           // rows row0, row0+1 share b
    const int2 jj = *reinterpret_cast<const int2*>(g_nbr + row0);

    const float4* s0 = reinterpret_cast<const float4*>(attr + ((size_t)b * LL + jj.x) * DD);
    const float4* s1 = reinterpret_cast<const float4*>(attr + ((size_t)b * LL + jj.y) * DD);
    float4* d0 = reinterpret_cast<float4*>(out_attr + (size_t)row0 * DD);
    float4* d1 = d0 + DD / 4;

    const float4 v0 = s0[lane];
    const float4 v1 = s1[lane];
    d0[lane] = v0;
    d1[lane] = v1;
}

extern "C" void kernel_launch(void* const* d_in, const int* in_sizes, int n_in,
                              void* d_out, int out_size)
{
    const float* frame = (const float*)d_in[0];
    const float* attr  = (const float*)d_in[1];
    if (n_in >= 2 && in_sizes[0] == BB * LL * DD) {   // defensive order check
        attr  = (const float*)d_in[0];
        frame = (const float*)d_in[1];
    }

    float* out        = (float*)d_out;
    float* out_euclid = out;                               // B*L*K*3
    float* out_attr   = out + (size_t)BB * LL * KNN * 3;   // B*L*K*D

    knn_kernel<<<dim3(LL / 16, BB), 512>>>(frame, out_euclid);

    const int rows = BB * LL * KNN;                        // 524288 rows
    gather_kernel<<<rows / 16, 256>>>(attr, out_attr);     // 2 rows per warp
}